// round 7
// baseline (speedup 1.0000x reference)
#include <cuda_runtime.h>
#include <math.h>

#define BB 8192
#define NN 4096
#define WBINS 1000
#define LSTRIDE 101        // L_CUTOFF + 1, row stride of sine_terms
#define LL 16              // truncated series (exp(-0.5*l(l+1)*0.36) < 5e-17 at l=14)
#define GRAD_GAUSS_THRES 0.6f
#define GPB 8              // batches per block
#define THREADS 512
#define SINE_STRIDE 1024   // padded row stride of g_sineT (zeros beyond WBINS)
#define TABROW 1002        // floats per table row (1001 used)

__device__ float g_sineT[LL * SINE_STRIDE];

// ---------------------------------------------------------------------------
// Kernel 0: transpose first LL columns of sine_terms, zero-pad to stride 1024
// ---------------------------------------------------------------------------
__global__ void transpose_kernel(const float* __restrict__ sine_terms) {
    int idx = blockIdx.x * blockDim.x + threadIdx.x;   // 0 .. LL*1024-1
    int l = idx >> 10;
    int w = idx & (SINE_STRIDE - 1);
    g_sineT[idx] = (w < WBINS) ? sine_terms[w * LSTRIDE + l] : 0.0f;
}

// ---------------------------------------------------------------------------
// Fused kernel. Per block: build 8 batches' single-float v-tables in SMEM,
//   u[idx] = pdf_pad[idx] * bw / (pdf_pad[idx+1] - pdf_pad[idx])   ( = left/grad )
//   v[idx] = u[idx] - (idx + 0.5) * bw                 (center folded in)
// from the truncated Legendre series (unnormalized pdf — normalization cancels),
// then evaluate 8*4096 omegas as  out = 1 / (v[idx] + w)
// == reference's grad_pdf / pdf_accurate. grad==0 -> v=inf -> out=0 (matches).
// pdf_pad = [pdf[0], pdf[0..999], pdf[998]].
// Phase 2 runs in TWO passes of 4 batches to keep live registers <= 32 so
// we fit 4 blocks/SM (reg-file bound: 512*32*4 = 64K regs).
// ---------------------------------------------------------------------------
__global__ __launch_bounds__(THREADS, 4)
void fused_kernel(const float* __restrict__ sigmas,
                  const float* __restrict__ omegas,
                  const float* __restrict__ omega_grid,
                  float* __restrict__ out) {
    __shared__ float  s_tab[GPB][TABROW];            // ~32 KB
    __shared__ __align__(16) float s_expT[LL][GPB];  // transposed series weights
    __shared__ float  s_edge[16][4];                 // per-warp boundary pdf values
    __shared__ float2 s_par[GPB];

    const int tid  = threadIdx.x;
    const int lane = tid & 31;
    const int wid  = tid >> 5;
    const int base = blockIdx.x * GPB;

    const float bw     = __ldg(&omega_grid[1]) - __ldg(&omega_grid[0]);
    const float inv_bw = 1.0f / bw;

    // ---- phase 1: per-batch params + series weights -------------------------
    if (tid < GPB) {
        float sg = sigmas[base + tid];
        s_par[tid] = make_float2(-1.0f / (sg * sg),
                                 (sg > GRAD_GAUSS_THRES) ? 1.0f : 0.0f);
    }
    if (tid < GPB * LL) {
        int l = tid >> 3;
        int g = tid & (GPB - 1);
        float sg = sigmas[base + g];
        s_expT[l][g] = expf(-0.5f * (float)(l * (l + 1)) * (sg * sg));
    }
    __syncthreads();

    // ---- phase 2: series, two passes of 4 batches ---------------------------
    // all 512 threads; thread t owns bins (2t, 2t+1)
    const float c1 = ((float)(2 * tid + 1) + 0.5f) * bw;   // center of entry 2t+1
    const float c2 = ((float)(2 * tid + 2) + 0.5f) * bw;   // center of entry 2t+2

    #pragma unroll 1
    for (int half = 0; half < 2; half++) {
        const int gb = half * 4;
        float a0[4], a1[4];
        #pragma unroll
        for (int g = 0; g < 4; g++) { a0[g] = 0.0f; a1[g] = 0.0f; }

        #pragma unroll
        for (int l = LL - 1; l >= 0; l--) {   // small terms first
            float2 sv = *reinterpret_cast<const float2*>(
                            &g_sineT[l * SINE_STRIDE + 2 * tid]);
            float4 ev = *reinterpret_cast<const float4*>(&s_expT[l][gb]);
            a0[0] = fmaf(ev.x, sv.x, a0[0]);  a1[0] = fmaf(ev.x, sv.y, a1[0]);
            a0[1] = fmaf(ev.y, sv.x, a0[1]);  a1[1] = fmaf(ev.y, sv.y, a1[1]);
            a0[2] = fmaf(ev.z, sv.x, a0[2]);  a1[2] = fmaf(ev.z, sv.y, a1[2]);
            a0[3] = fmaf(ev.w, sv.x, a0[3]);  a1[3] = fmaf(ev.w, sv.y, a1[3]);
        }

        // per-warp edge values: warp w stores its lane-0 a0 (pdf[64w])
        if (lane == 0) {
            #pragma unroll
            for (int g = 0; g < 4; g++) s_edge[wid][g] = a0[g];
        }
        __syncthreads();

        // n0[g] = pdf[2t+2]; t=499 overrides per pdf_pad[1001]=pdf[998]
        float n0[4];
        #pragma unroll
        for (int g = 0; g < 4; g++)
            n0[g] = __shfl_down_sync(0xffffffffu, a0[g], 1);
        if (lane == 31 && wid < 15) {
            #pragma unroll
            for (int g = 0; g < 4; g++) n0[g] = s_edge[wid + 1][g];
        }
        if (tid == WBINS / 2 - 1) {
            #pragma unroll
            for (int g = 0; g < 4; g++) n0[g] = a0[g];
        }

        if (tid < WBINS / 2) {
            #pragma unroll
            for (int g = 0; g < 4; g++) {
                float u1 = __fdiv_rn(a0[g] * bw, a1[g] - a0[g]);
                float u2 = __fdiv_rn(a1[g] * bw, n0[g] - a1[g]);
                s_tab[gb + g][2 * tid + 1] = u1 - c1;
                s_tab[gb + g][2 * tid + 2] = u2 - c2;
                if (tid == 0) s_tab[gb + g][0] = __int_as_float(0x7f800000);
            }
        }
        __syncthreads();   // also protects s_edge reuse next pass
    }

    // ---- phase 3: evaluate 8*4096 omegas ------------------------------------
    const float4* om4  = reinterpret_cast<const float4*>(omegas)
                         + (size_t)blockIdx.x * (GPB * NN / 4);
    float4*       out4 = reinterpret_cast<float4*>(out)
                         + (size_t)blockIdx.x * (GPB * NN / 4);

    #pragma unroll 4
    for (int j = 0; j < GPB * NN / 4 / THREADS; j++) {   // 16 iters
        int i  = j * THREADS + tid;
        int bl = i >> 10;                                // NN/4 = 1024 float4/batch
        float2 p  = s_par[bl];
        float4 om = __ldcs(om4 + i);
        float4 r;
        if (p.y > 0.5f) {
            const float* row = s_tab[bl];
            #pragma unroll
            for (int c = 0; c < 4; c++) {
                float w = (&om.x)[c];
                int idx = __float2int_rd(fmaf(w, inv_bw, 0.5f));
                idx = min(idx, WBINS);                   // w in [0,pi) => idx >= 0
                (&r.x)[c] = __fdividef(1.0f, row[idx] + w);
            }
        } else {
            r.x = om.x * p.x; r.y = om.y * p.x;
            r.z = om.z * p.x; r.w = om.w * p.x;
        }
        __stcs(out4 + i, r);
    }
}

// ---------------------------------------------------------------------------
extern "C" void kernel_launch(void* const* d_in, const int* in_sizes, int n_in,
                              void* d_out, int out_size) {
    const float* sigmas     = (const float*)d_in[0];   // [B]
    const float* omegas     = (const float*)d_in[1];   // [B, N]
    const float* omega_grid = (const float*)d_in[2];   // [WBINS]
    const float* sine_terms = (const float*)d_in[4];   // [WBINS, 101]

    transpose_kernel<<<LL * SINE_STRIDE / 256, 256>>>(sine_terms);
    fused_kernel<<<BB / GPB, THREADS>>>(sigmas, omegas, omega_grid, (float*)d_out);
}

// round 8
// speedup vs baseline: 1.0942x; 1.0942x over previous
#include <cuda_runtime.h>
#include <math.h>

#define BB 8192
#define NN 4096
#define WBINS 1000
#define LSTRIDE 101        // L_CUTOFF + 1, row stride of sine_terms
#define LL 16              // truncated series (exp(-0.5*l(l+1)*0.36) < 5e-17 at l=14)
#define GRAD_GAUSS_THRES 0.6f
#define GPB 8              // batches per block
#define THREADS 512
#define SINE_STRIDE 1024   // padded row stride of g_sineT (zeros beyond WBINS)
#define TABROW 1002        // floats per table row (1001 used)

__device__ float g_sineT[LL * SINE_STRIDE];

// ---------------------------------------------------------------------------
// Kernel 0: transpose first LL columns of sine_terms, zero-pad to stride 1024
// ---------------------------------------------------------------------------
__global__ void transpose_kernel(const float* __restrict__ sine_terms) {
    int idx = blockIdx.x * blockDim.x + threadIdx.x;   // 0 .. LL*1024-1
    int l = idx >> 10;
    int w = idx & (SINE_STRIDE - 1);
    g_sineT[idx] = (w < WBINS) ? sine_terms[w * LSTRIDE + l] : 0.0f;
}

// ---------------------------------------------------------------------------
// Fused kernel. Per block: build 8 batches' single-float v-tables in SMEM,
//   u[idx] = pdf_pad[idx] * bw / (pdf_pad[idx+1] - pdf_pad[idx])   ( = left/grad )
//   v[idx] = u[idx] - (idx + 0.5) * bw                 (center folded in)
// from the truncated Legendre series (unnormalized pdf — normalization cancels),
// then evaluate 8*4096 omegas as  out = 1 / (v[idx] + w)
// == reference's grad_pdf / pdf_accurate. grad==0 -> v=inf -> out=0 (matches).
// pdf_pad = [pdf[0], pdf[0..999], pdf[998]].
// idx = floor(fma(w, inv_bw, 0.5)) <= 1000 always (w < pi_fp32), no clamp.
// ---------------------------------------------------------------------------
__global__ __launch_bounds__(THREADS, 4)
void fused_kernel(const float* __restrict__ sigmas,
                  const float* __restrict__ omegas,
                  const float* __restrict__ omega_grid,
                  float* __restrict__ out) {
    __shared__ float  s_tab[GPB][TABROW];            // ~32 KB
    __shared__ __align__(16) float s_expT[LL][GPB];  // transposed series weights
    __shared__ float  s_edge[16][4];                 // per-warp boundary pdf values
    __shared__ float2 s_par[GPB];

    const int tid  = threadIdx.x;
    const int lane = tid & 31;
    const int wid  = tid >> 5;
    const int base = blockIdx.x * GPB;

    const float bw     = __ldg(&omega_grid[1]) - __ldg(&omega_grid[0]);
    const float inv_bw = 1.0f / bw;

    // ---- phase 1: per-batch params + series weights -------------------------
    if (tid < GPB) {
        float sg = sigmas[base + tid];
        s_par[tid] = make_float2(-1.0f / (sg * sg),
                                 (sg > GRAD_GAUSS_THRES) ? 1.0f : 0.0f);
    }
    if (tid < GPB * LL) {
        int l = tid >> 3;
        int g = tid & (GPB - 1);
        float sg = sigmas[base + g];
        s_expT[l][g] = expf(-0.5f * (float)(l * (l + 1)) * (sg * sg));
    }
    __syncthreads();

    // ---- phase 2: series, two passes of 4 batches (regs <= 32) --------------
    const float c1 = ((float)(2 * tid + 1) + 0.5f) * bw;   // center of entry 2t+1
    const float c2 = ((float)(2 * tid + 2) + 0.5f) * bw;   // center of entry 2t+2

    #pragma unroll 1
    for (int half = 0; half < 2; half++) {
        const int gb = half * 4;
        float a0[4], a1[4];
        #pragma unroll
        for (int g = 0; g < 4; g++) { a0[g] = 0.0f; a1[g] = 0.0f; }

        #pragma unroll
        for (int l = LL - 1; l >= 0; l--) {   // small terms first
            float2 sv = *reinterpret_cast<const float2*>(
                            &g_sineT[l * SINE_STRIDE + 2 * tid]);
            float4 ev = *reinterpret_cast<const float4*>(&s_expT[l][gb]);
            a0[0] = fmaf(ev.x, sv.x, a0[0]);  a1[0] = fmaf(ev.x, sv.y, a1[0]);
            a0[1] = fmaf(ev.y, sv.x, a0[1]);  a1[1] = fmaf(ev.y, sv.y, a1[1]);
            a0[2] = fmaf(ev.z, sv.x, a0[2]);  a1[2] = fmaf(ev.z, sv.y, a1[2]);
            a0[3] = fmaf(ev.w, sv.x, a0[3]);  a1[3] = fmaf(ev.w, sv.y, a1[3]);
        }

        if (lane == 0) {
            #pragma unroll
            for (int g = 0; g < 4; g++) s_edge[wid][g] = a0[g];
        }
        __syncthreads();

        // n0[g] = pdf[2t+2]; t=499 overrides per pdf_pad[1001]=pdf[998]
        float n0[4];
        #pragma unroll
        for (int g = 0; g < 4; g++)
            n0[g] = __shfl_down_sync(0xffffffffu, a0[g], 1);
        if (lane == 31 && wid < 15) {
            #pragma unroll
            for (int g = 0; g < 4; g++) n0[g] = s_edge[wid + 1][g];
        }
        if (tid == WBINS / 2 - 1) {
            #pragma unroll
            for (int g = 0; g < 4; g++) n0[g] = a0[g];
        }

        if (tid < WBINS / 2) {
            #pragma unroll
            for (int g = 0; g < 4; g++) {
                float u1 = __fdiv_rn(a0[g] * bw, a1[g] - a0[g]);
                float u2 = __fdiv_rn(a1[g] * bw, n0[g] - a1[g]);
                s_tab[gb + g][2 * tid + 1] = u1 - c1;
                s_tab[gb + g][2 * tid + 2] = u2 - c2;
                if (tid == 0) s_tab[gb + g][0] = __int_as_float(0x7f800000);
            }
        }
        __syncthreads();   // also protects s_edge reuse next pass
    }

    // ---- phase 3: evaluate, one batch row at a time --------------------------
    // Row-uniform p/row/branch hoisted; both float4 chunks' LDGs issued up
    // front so the 2nd chunk's DRAM latency overlaps the 1st chunk's math.
    const float4* om4  = reinterpret_cast<const float4*>(omegas)
                         + (size_t)blockIdx.x * (GPB * NN / 4);
    float4*       out4 = reinterpret_cast<float4*>(out)
                         + (size_t)blockIdx.x * (GPB * NN / 4);

    #pragma unroll 1
    for (int bl = 0; bl < GPB; bl++) {
        const int i0 = bl * (NN / 4) + tid;            // chunk 0
        const int i1 = i0 + THREADS;                   // chunk 1
        float2 p = s_par[bl];
        float4 om0 = __ldcs(om4 + i0);
        float4 om1 = __ldcs(om4 + i1);
        float4 r0, r1;
        if (p.y > 0.5f) {
            const float* row = s_tab[bl];
            #pragma unroll
            for (int c = 0; c < 4; c++) {
                float w = (&om0.x)[c];
                int idx = __float2int_rd(fmaf(w, inv_bw, 0.5f));
                (&r0.x)[c] = __fdividef(1.0f, row[idx] + w);
            }
            __stcs(out4 + i0, r0);
            #pragma unroll
            for (int c = 0; c < 4; c++) {
                float w = (&om1.x)[c];
                int idx = __float2int_rd(fmaf(w, inv_bw, 0.5f));
                (&r1.x)[c] = __fdividef(1.0f, row[idx] + w);
            }
            __stcs(out4 + i1, r1);
        } else {
            r0.x = om0.x * p.x; r0.y = om0.y * p.x;
            r0.z = om0.z * p.x; r0.w = om0.w * p.x;
            __stcs(out4 + i0, r0);
            r1.x = om1.x * p.x; r1.y = om1.y * p.x;
            r1.z = om1.z * p.x; r1.w = om1.w * p.x;
            __stcs(out4 + i1, r1);
        }
    }
}

// ---------------------------------------------------------------------------
extern "C" void kernel_launch(void* const* d_in, const int* in_sizes, int n_in,
                              void* d_out, int out_size) {
    const float* sigmas     = (const float*)d_in[0];   // [B]
    const float* omegas     = (const float*)d_in[1];   // [B, N]
    const float* omega_grid = (const float*)d_in[2];   // [WBINS]
    const float* sine_terms = (const float*)d_in[4];   // [WBINS, 101]

    transpose_kernel<<<LL * SINE_STRIDE / 256, 256>>>(sine_terms);
    fused_kernel<<<BB / GPB, THREADS>>>(sigmas, omegas, omega_grid, (float*)d_out);
}